// round 8
// baseline (speedup 1.0000x reference)
#include <cuda_runtime.h>
#include <cuda_fp16.h>
#include <cstdint>

// Problem constants
#define DD    256
#define HW    4096
#define NTOK  65536          // 16 * 4096
#define KCB   2048
#define QSIZE 16777216       // 16 * 256 * 4096
// out layout (float32): [0..QSIZE) q, [QSIZE] loss, [QSIZE+1] codebook_loss,
// [QSIZE+2] commitment_loss, [QSIZE+3 .. +KCB) counts

#define EPS_SEL 3.0e-3f

// Scratch (device globals — no allocs allowed)
__device__ float   g_c2[KCB];
__device__ float   g_z2[NTOK];
__device__ float   g_zt[(size_t)NTOK * DD];    // z fp32 token-major (64 MB)
__device__ __half2 g_zp[(size_t)NTOK * 128];   // z fp16 d-pair planes (32 MB)
__device__ __half2 g_cph[(size_t)KCB * 128];   // codebook fp16 d-pairs (1 MB)
__device__ int     g_idx[NTOK];

// ---------------------------------------------------------------------------
// exact fp32 rescore; dist rounding matches rounds 1-7 (passed at 2.38e-7)
__device__ __noinline__ unsigned long long rescore(int n, int k,
                                                   const float* __restrict__ cb) {
    const float4* zp = (const float4*)(g_zt + (size_t)n * DD);
    const float4* cr = (const float4*)(cb + (size_t)k * DD);
    float s0 = 0.f, s1 = 0.f, s2 = 0.f, s3 = 0.f;
    #pragma unroll 8
    for (int i = 0; i < 64; i++) {
        float4 a = zp[i], b = cr[i];
        s0 = fmaf(a.x, b.x, s0); s1 = fmaf(a.y, b.y, s1);
        s2 = fmaf(a.z, b.z, s2); s3 = fmaf(a.w, b.w, s3);
    }
    float dot  = (s0 + s1) + (s2 + s3);
    float dist = fmaf(-2.0f, dot, g_z2[n] + g_c2[k]);
    return ((unsigned long long)__float_as_uint(dist) << 32) | (unsigned)k;
}

// ---------------------------------------------------------------------------
__global__ void init_out_kernel(float* out) {
    int i = threadIdx.x + blockIdx.x * blockDim.x;
    if (i < 3 + KCB) out[QSIZE + i] = 0.0f;
}

__global__ void c2_kernel(const float* __restrict__ cb) {
    int warp = (threadIdx.x >> 5) + blockIdx.x * (blockDim.x >> 5);
    int lane = threadIdx.x & 31;
    if (warp >= KCB) return;
    const float* row = cb + (size_t)warp * DD;
    float s = 0.f;
    #pragma unroll
    for (int d = lane; d < DD; d += 32) { float v = row[d]; s = fmaf(v, v, s); }
    #pragma unroll
    for (int off = 16; off; off >>= 1) s += __shfl_down_sync(0xffffffffu, s, off);
    if (lane == 0) g_c2[warp] = s;
}

__global__ void z2_kernel(const float* __restrict__ z) {
    int n = threadIdx.x + blockIdx.x * blockDim.x;
    if (n >= NTOK) return;
    int b = n >> 12, hw = n & 4095;
    const float* p = z + (size_t)b * (DD * HW) + hw;
    float s = 0.f;
    #pragma unroll 8
    for (int d = 0; d < DD; d++) { float v = p[(size_t)d * HW]; s = fmaf(v, v, s); }
    g_z2[n] = s;
}

// pack z into fp16 d-pair planes: g_zp[(b*128+d2)*4096 + hw] = (z[2d2], z[2d2+1])
__global__ void pz_kernel(const float* __restrict__ z) {
    int idx = threadIdx.x + blockIdx.x * blockDim.x;   // over 16*128*4096
    int row = idx >> 12, hw = idx & 4095;
    int b = row >> 7, d2 = row & 127;
    const float* p = z + (size_t)b * (DD * HW) + (size_t)(2 * d2) * HW + hw;
    g_zp[(size_t)idx] = __floats2half2_rn(p[0], p[HW]);
}

// pack codebook fp16 d-pairs
__global__ void pcb_kernel(const float* __restrict__ cb) {
    int idx = threadIdx.x + blockIdx.x * blockDim.x;   // over 2048*128
    if (idx >= KCB * 128) return;
    float2 v = *(const float2*)(cb + (size_t)idx * 2);
    g_cph[idx] = __floats2half2_rn(v.x, v.y);
}

// transpose z -> token-major fp32 (for exact rescore)
__global__ __launch_bounds__(256)
void tz_kernel(const float* __restrict__ z) {
    __shared__ float t[64][65];
    const int bx = blockIdx.x;
    const int hw0 = (bx & 63) * 64;
    const int d0  = ((bx >> 6) & 3) * 64;
    const int b   = bx >> 8;
    const float* zb = z + (size_t)b * (DD * HW);
    const int tid = threadIdx.x;
    #pragma unroll
    for (int it = 0; it < 16; it++) {
        int p = tid + it * 256;
        int dd = p >> 6, r = p & 63;
        t[dd][r] = zb[(size_t)(d0 + dd) * HW + hw0 + r];
    }
    __syncthreads();
    #pragma unroll
    for (int it = 0; it < 16; it++) {
        int p = tid + it * 256;
        int r = p >> 6, dd = p & 63;
        size_t n = (size_t)b * 4096 + hw0 + r;
        g_zt[n * 256 + d0 + dd] = t[dd][r];
    }
}

// ---------------------------------------------------------------------------
// Main HFMA2 kernel: 128 tokens/CTA x 2048 codes, fp16 half2 filter GEMM
// (2 MAC/slot on the fma pipe) + running-min scan + inline exact rescore.
// ---------------------------------------------------------------------------
__global__ __launch_bounds__(256, 2)
void vq_half_kernel(const float* __restrict__ cb) {
    __shared__ __half2 As[8][128];           // [d2][token]
    __shared__ __half2 Bs[8][132];           // [d2][code], padded
    __shared__ unsigned long long red[128][16];

    const int tid = threadIdx.x;
    const int tx = tid & 15;                 // code micro-dim
    const int ty = tid >> 4;                 // token micro-dim
    const int n0 = blockIdx.x * 128;
    const int b  = n0 >> 12;
    const int hw0 = n0 & 4095;

    float m[8];
    unsigned long long key[8];
    #pragma unroll
    for (int i = 0; i < 8; i++) { m[i] = __int_as_float(0x7f800000); key[i] = ~0ULL; }

    const int a_dd = tid >> 5;               // 0..7  (d2 row)
    const int a_tq = (tid & 31) * 4;         // token offset (4 half2 = 16B)
    const int b_kk = tid >> 1;               // 0..127 (code)
    const int b_p  = (tid & 1) * 4;          // d2 offset

    const __half2* zrow = g_zp + ((size_t)(b * 128) * 4096 + hw0);

    for (int kc = 0; kc < KCB; kc += 128) {
        __half2 acc[8][8];
        #pragma unroll
        for (int i = 0; i < 8; i++)
            #pragma unroll
            for (int j = 0; j < 8; j++) acc[i][j] = __floats2half2_rn(0.f, 0.f);

        for (int dc2 = 0; dc2 < 128; dc2 += 8) {
            uint4 av = *(const uint4*)(zrow + (size_t)(dc2 + a_dd) * 4096 + a_tq);
            uint4 bv = *(const uint4*)(g_cph + (size_t)(kc + b_kk) * 128 + dc2 + b_p);
            __syncthreads();
            *(uint4*)&As[a_dd][a_tq] = av;
            Bs[b_p + 0][b_kk] = ((const __half2*)&bv)[0];
            Bs[b_p + 1][b_kk] = ((const __half2*)&bv)[1];
            Bs[b_p + 2][b_kk] = ((const __half2*)&bv)[2];
            Bs[b_p + 3][b_kk] = ((const __half2*)&bv)[3];
            __syncthreads();

            #pragma unroll
            for (int d2 = 0; d2 < 8; d2++) {
                __half2 a2[8], b2[8];
                #pragma unroll
                for (int i = 0; i < 8; i++) a2[i] = As[d2][ty + 16 * i];
                #pragma unroll
                for (int j = 0; j < 8; j++) b2[j] = Bs[d2][tx + 16 * j];
                #pragma unroll
                for (int i = 0; i < 8; i++)
                    #pragma unroll
                    for (int j = 0; j < 8; j++)
                        acc[i][j] = __hfma2(a2[i], b2[j], acc[i][j]);
            }
        }

        // scan: approx score + inline exact rescore of near-min candidates
        #pragma unroll
        for (int j = 0; j < 8; j++) {
            const int k = kc + tx + 16 * j;
            const float c2k = g_c2[k];
            #pragma unroll
            for (int i = 0; i < 8; i++) {
                float2 f = __half22float2(acc[i][j]);
                float s = fmaf(-2.0f, f.x + f.y, c2k);
                if (s < m[i]) m[i] = s;
                if (s <= m[i] + EPS_SEL) {
                    unsigned long long kx = rescore(n0 + ty + 16 * i, k, cb);
                    if (kx < key[i]) key[i] = kx;
                }
            }
        }
    }

    // cross-thread argmin reduction (keys carry exact dist bits + smallest-k)
    #pragma unroll
    for (int i = 0; i < 8; i++) red[ty + 16 * i][tx] = key[i];
    __syncthreads();
    if (tid < 128) {
        unsigned long long mm = red[tid][0];
        #pragma unroll
        for (int t = 1; t < 16; t++) {
            unsigned long long v = red[tid][t];
            if (v < mm) mm = v;
        }
        g_idx[n0 + tid] = (int)(mm & 0xFFFFFFFFu);
    }
}

// ---------------------------------------------------------------------------
// Output epilogue: q (straight-through), counts, fused SSE
// ---------------------------------------------------------------------------
__global__ __launch_bounds__(256)
void vq_out_kernel(const float* __restrict__ z, const float* __restrict__ cb,
                   float* __restrict__ out) {
    __shared__ float lred[8];
    const int tid = threadIdx.x;
    const int n0 = blockIdx.x * 128;
    const int b = n0 >> 12, hw0 = n0 & 4095;

    if (tid < 128) atomicAdd(out + QSIZE + 3 + g_idx[n0 + tid], 1.0f);

    const int tok  = tid & 127;
    const int half = tid >> 7;
    const int kidx = g_idx[n0 + tok];
    const float* crow = cb + (size_t)kidx * DD;
    float* qbase = out + (size_t)b * (DD * HW) + hw0 + tok;
    const float* zb2 = z + (size_t)b * (DD * HW) + hw0 + tok;
    float lsum = 0.f;
    #pragma unroll 4
    for (int d = half * 128; d < half * 128 + 128; d++) {
        float c  = crow[d];
        float zz = zb2[(size_t)d * HW];
        float df = zz - c;
        lsum = fmaf(df, df, lsum);
        qbase[(size_t)d * HW] = zz + (c - zz);   // == reference ST rounding
    }
    #pragma unroll
    for (int off = 16; off; off >>= 1) lsum += __shfl_down_sync(0xffffffffu, lsum, off);
    if ((tid & 31) == 0) lred[tid >> 5] = lsum;
    __syncthreads();
    if (tid == 0) {
        float s = 0.f;
        #pragma unroll
        for (int w = 0; w < 8; w++) s += lred[w];
        atomicAdd(out + QSIZE + 1, s);
    }
}

__global__ void finalize_kernel(float* out) {
    float sse = out[QSIZE + 1];
    float mse = sse / (float)((size_t)NTOK * DD);
    out[QSIZE]     = fmaf(0.25f, mse, mse);
    out[QSIZE + 1] = mse;
    out[QSIZE + 2] = mse;
}

// ---------------------------------------------------------------------------
extern "C" void kernel_launch(void* const* d_in, const int* in_sizes, int n_in,
                              void* d_out, int out_size) {
    const float* z  = (const float*)d_in[0];     // (16, 256, 64, 64)
    const float* cb = (const float*)d_in[1];     // (2048, 256)
    float* out = (float*)d_out;

    init_out_kernel<<<9, 256>>>(out);
    c2_kernel<<<KCB / 8, 256>>>(cb);
    z2_kernel<<<NTOK / 256, 256>>>(z);
    pcb_kernel<<<KCB * 128 / 256, 256>>>(cb);
    pz_kernel<<<NTOK * 128 / 256, 256>>>(z);
    tz_kernel<<<4096, 256>>>(z);
    vq_half_kernel<<<NTOK / 128, 256>>>(cb);
    vq_out_kernel<<<NTOK / 128, 256>>>(z, cb, out);
    finalize_kernel<<<1, 1>>>(out);
}